// round 6
// baseline (speedup 1.0000x reference)
#include <cuda_runtime.h>
#include <cuda_bf16.h>
#include <cfloat>

// ColorReducer: out[b,:,h,w] = palette[argmin_k ||x[b,:,h,w] - palette[k]||^2]
// argmin_k ||p-c||^2 == argmax_k s_k, s_k = p.c - 0.5*||c||^2.
//
// Round-6:
//  - __constant__ palette; hot loop reads via LDC.128. LDC->LDC structural floor
//    is 8 cyc => const port was the round-5 wall at 0.5 LDC/elem. PPT=8 halves
//    it to 0.25 LDC/elem.
//  - fma.rn.f32x2 packed FMA (2 pixels/instruction, bit-identical to FFMA.rn)
//  - tournament argmax over groups of 4 colors; winning group recomputed with
//    identical FMA order => exact equality match, first-index tie rule.
//  - only packed pixel regs live in the hot loop; scalars unpacked in finale.

#define CR_HW 262144
#define PPT 8

#define F2FMA(d, a, b, c) \
    asm("fma.rn.f32x2 %0, %1, %2, %3;" : "=l"(d) : "l"(a), "l"(b), "l"(c))
#define F2PACK(d, lo, hi) \
    asm("mov.b64 %0, {%1, %2};" : "=l"(d) : "f"(lo), "f"(hi))
#define F2UNPACK(lo, hi, v) \
    asm("mov.b64 {%0, %1}, %2;" : "=f"(lo), "=f"(hi) : "l"(v))

typedef unsigned long long ull;

struct PalConst {
    // [k][0] = {cx,cx},{cy,cy}; [k][1] = {cz,cz},{h,h}
    ulonglong2 pal2[64][2];
    float4     palc[64];
};

__constant__ __align__(16) PalConst c_pal;
__device__  __align__(16) PalConst g_stage;

__global__ void prep_kernel(const float* __restrict__ pal)
{
    int t = threadIdx.x;
    if (t < 64) {
        float cx = pal[t * 3 + 0];
        float cy = pal[t * 3 + 1];
        float cz = pal[t * 3 + 2];
        float h  = -0.5f * (cx * cx + cy * cy + cz * cz);
        ull uxx, uyy, uzz, uhh;
        F2PACK(uxx, cx, cx);
        F2PACK(uyy, cy, cy);
        F2PACK(uzz, cz, cz);
        F2PACK(uhh, h,  h);
        g_stage.pal2[t][0] = make_ulonglong2(uxx, uyy);
        g_stage.pal2[t][1] = make_ulonglong2(uzz, uhh);
        g_stage.palc[t]    = make_float4(cx, cy, cz, h);
    }
}

__global__ void __launch_bounds__(128, 6)
color_reduce_c_kernel(const float* __restrict__ x,
                      float* __restrict__ out,
                      int npix)
{
    // smem copy of compact palette (same bits as constants) for the
    // divergent-index finale + gather only.
    __shared__ float4 spalc[64];
    int t = threadIdx.x;
    if (t < 64) spalc[t] = c_pal.palc[t];
    __syncthreads();

    int gid = blockIdx.x * blockDim.x + t;
    int i0  = gid * PPT;
    if (i0 >= npix) return;

    int b = i0 >> 18;             // / CR_HW
    int q = i0 & (CR_HW - 1);

    const float* base  = x   + (size_t)b * 3 * CR_HW + q;
    float*       obase = out + (size_t)b * 3 * CR_HW + q;

    if (i0 + PPT - 1 < npix) {
        // 8 pixels: two float4 per channel plane; keep only packed pairs live.
        ull rp[4], gp[4], bp[4];
        {
            float4 v0 = *reinterpret_cast<const float4*>(base);
            float4 v1 = *reinterpret_cast<const float4*>(base + 4);
            F2PACK(rp[0], v0.x, v0.y); F2PACK(rp[1], v0.z, v0.w);
            F2PACK(rp[2], v1.x, v1.y); F2PACK(rp[3], v1.z, v1.w);
            v0 = *reinterpret_cast<const float4*>(base + CR_HW);
            v1 = *reinterpret_cast<const float4*>(base + CR_HW + 4);
            F2PACK(gp[0], v0.x, v0.y); F2PACK(gp[1], v0.z, v0.w);
            F2PACK(gp[2], v1.x, v1.y); F2PACK(gp[3], v1.z, v1.w);
            v0 = *reinterpret_cast<const float4*>(base + 2 * CR_HW);
            v1 = *reinterpret_cast<const float4*>(base + 2 * CR_HW + 4);
            F2PACK(bp[0], v0.x, v0.y); F2PACK(bp[1], v0.z, v0.w);
            F2PACK(bp[2], v1.x, v1.y); F2PACK(bp[3], v1.z, v1.w);
        }

        float best[PPT];
        int   bgrp[PPT];
#pragma unroll
        for (int p = 0; p < PPT; p++) { best[p] = -FLT_MAX; bgrp[p] = 0; }

#pragma unroll
        for (int g = 0; g < 16; g++) {
            // 4 colors' packed palette: 8x LDC.128, reused across 8 pixels
            ull cxx[4], cyy[4], czz[4], chh[4];
#pragma unroll
            for (int c = 0; c < 4; c++) {
                ulonglong2 v0 = c_pal.pal2[g * 4 + c][0];
                ulonglong2 v1 = c_pal.pal2[g * 4 + c][1];
                cxx[c] = v0.x; cyy[c] = v0.y; czz[c] = v1.x; chh[c] = v1.y;
            }
#pragma unroll
            for (int pp = 0; pp < 4; pp++) {   // 4 pixel pairs
                float s[4][2];
#pragma unroll
                for (int c = 0; c < 4; c++) {
                    ull sv;
                    F2FMA(sv, bp[pp], czz[c], chh[c]);
                    F2FMA(sv, gp[pp], cyy[c], sv);
                    F2FMA(sv, rp[pp], cxx[c], sv);
                    F2UNPACK(s[c][0], s[c][1], sv);
                }
#pragma unroll
                for (int half = 0; half < 2; half++) {
                    int p = 2 * pp + half;
                    float m = fmaxf(fmaxf(s[0][half], s[1][half]),
                                    fmaxf(s[2][half], s[3][half]));
                    if (m > best[p]) { best[p] = m; bgrp[p] = g; }
                }
            }
        }

        // finale (cold): unpack pixel scalars, recompute winning group's 4
        // scores with identical FMA order -> exact equality, first index wins.
        float rr[PPT], gg[PPT], bb[PPT];
#pragma unroll
        for (int pp = 0; pp < 4; pp++) {
            F2UNPACK(rr[2 * pp], rr[2 * pp + 1], rp[pp]);
            F2UNPACK(gg[2 * pp], gg[2 * pp + 1], gp[pp]);
            F2UNPACK(bb[2 * pp], bb[2 * pp + 1], bp[pp]);
        }

        float4 cc[PPT];
#pragma unroll
        for (int p = 0; p < PPT; p++) {
            int k0 = bgrp[p] * 4;
            float4 c0 = spalc[k0 + 0];
            float4 c1 = spalc[k0 + 1];
            float4 c2 = spalc[k0 + 2];
            float4 c3 = spalc[k0 + 3];
            float px = rr[p], py = gg[p], pz = bb[p];
            float s0 = fmaf(px, c0.x, fmaf(py, c0.y, fmaf(pz, c0.z, c0.w)));
            float s1 = fmaf(px, c1.x, fmaf(py, c1.y, fmaf(pz, c1.z, c1.w)));
            float s2 = fmaf(px, c2.x, fmaf(py, c2.y, fmaf(pz, c2.z, c2.w)));
            float s3 = fmaf(px, c3.x, fmaf(py, c3.y, fmaf(pz, c3.z, c3.w)));
            int j = 3;
            if (s2 == best[p]) j = 2;
            if (s1 == best[p]) j = 1;
            if (s0 == best[p]) j = 0;
            cc[p] = spalc[k0 + j];
        }

        *reinterpret_cast<float4*>(obase) =
            make_float4(cc[0].x, cc[1].x, cc[2].x, cc[3].x);
        *reinterpret_cast<float4*>(obase + 4) =
            make_float4(cc[4].x, cc[5].x, cc[6].x, cc[7].x);
        *reinterpret_cast<float4*>(obase + CR_HW) =
            make_float4(cc[0].y, cc[1].y, cc[2].y, cc[3].y);
        *reinterpret_cast<float4*>(obase + CR_HW + 4) =
            make_float4(cc[4].y, cc[5].y, cc[6].y, cc[7].y);
        *reinterpret_cast<float4*>(obase + 2 * CR_HW) =
            make_float4(cc[0].z, cc[1].z, cc[2].z, cc[3].z);
        *reinterpret_cast<float4*>(obase + 2 * CR_HW + 4) =
            make_float4(cc[4].z, cc[5].z, cc[6].z, cc[7].z);
    } else {
        for (int i = i0; i < npix; i++) {
            int b2 = i >> 18;
            int q2 = i & (CR_HW - 1);
            const float* pb2 = x + (size_t)b2 * 3 * CR_HW + q2;
            float px = pb2[0], py = pb2[CR_HW], pz = pb2[2 * CR_HW];
            float bestv = -FLT_MAX; int bk = 0;
            for (int k = 0; k < 64; k++) {
                float4 c = spalc[k];
                float s = fmaf(px, c.x, fmaf(py, c.y, fmaf(pz, c.z, c.w)));
                if (s > bestv) { bestv = s; bk = k; }
            }
            float4 c = spalc[bk];
            float* ob = out + (size_t)b2 * 3 * CR_HW + q2;
            ob[0] = c.x; ob[CR_HW] = c.y; ob[2 * CR_HW] = c.z;
        }
    }
}

// generic fallback (any shape / ncol)
__global__ void color_reduce_generic_kernel(const float* __restrict__ x,
                                            const float* __restrict__ pal,
                                            float* __restrict__ out,
                                            int npix, int hw, int ncol)
{
    extern __shared__ float4 gpal[];
    int t = threadIdx.x;
    for (int k = t; k < ncol; k += blockDim.x) {
        float cx = pal[k * 3 + 0], cy = pal[k * 3 + 1], cz = pal[k * 3 + 2];
        gpal[k] = make_float4(cx, cy, cz, -0.5f * (cx * cx + cy * cy + cz * cz));
    }
    __syncthreads();
    int i = blockIdx.x * blockDim.x + t;
    if (i >= npix) return;
    int b = i / hw, q = i - b * hw;
    const float* pb = x + (size_t)b * 3 * (size_t)hw + q;
    float px = pb[0], py = pb[hw], pz = pb[2 * hw];
    float bestv = -FLT_MAX; int bk = 0;
    for (int k = 0; k < ncol; k++) {
        float4 c = gpal[k];
        float s = fmaf(px, c.x, fmaf(py, c.y, fmaf(pz, c.z, c.w)));
        if (s > bestv) { bestv = s; bk = k; }
    }
    float4 c = gpal[bk];
    float* ob = out + (size_t)b * 3 * (size_t)hw + q;
    ob[0] = c.x; ob[hw] = c.y; ob[2 * hw] = c.z;
}

extern "C" void kernel_launch(void* const* d_in, const int* in_sizes, int n_in,
                              void* d_out, int out_size)
{
    const float* x   = (const float*)d_in[0];
    const float* pal = (const float*)d_in[1];
    float*       out = (float*)d_out;

    int nelem = in_sizes[0];
    int ncol  = in_sizes[1] / 3;
    int npix  = nelem / 3;

    if (ncol == 64 && nelem % (3 * CR_HW) == 0) {
        prep_kernel<<<1, 64>>>(pal);

        void* ps = nullptr;
        cudaGetSymbolAddress(&ps, g_stage);
        cudaMemcpyToSymbolAsync(c_pal, ps, sizeof(PalConst), 0,
                                cudaMemcpyDeviceToDevice, 0);

        int threads = 128;
        int groups  = (npix + PPT - 1) / PPT;
        int blocks  = (groups + threads - 1) / threads;
        color_reduce_c_kernel<<<blocks, threads>>>(x, out, npix);
    } else {
        int hw = npix;
        if (nelem % (3 * CR_HW) == 0) hw = CR_HW;
        int threads = 256;
        int blocks  = (npix + threads - 1) / threads;
        color_reduce_generic_kernel<<<blocks, threads, ncol * sizeof(float4)>>>(
            x, pal, out, npix, hw, ncol);
    }
}

// round 7
// speedup vs baseline: 1.1415x; 1.1415x over previous
#include <cuda_runtime.h>
#include <cuda_bf16.h>
#include <cfloat>

// ColorReducer: out[b,:,h,w] = palette[argmin_k ||x[b,:,h,w] - palette[k]||^2]
// argmin_k ||p-c||^2 == argmax_k s_k, s_k = p.c - 0.5*||c||^2.
//
// Round-7:
//  - FLIPPED packing: fma.rn.f32x2 packs (1 pixel x 2 colors) instead of
//    (2 pixels x 1 color). Palette stored color-PAIR-packed => 1 LDC.128 per
//    color instead of 2 (const-port floor LDC->LDC=8cyc was the wall).
//    Pixel operand duplicated {r,r} once per pixel, reused across 64 colors.
//  - tournament argmax over groups of 4 colors; winning group recomputed with
//    identical FMA order => exact equality match, first-index tie rule.
//  - all FMA chains keep the same nesting (b innermost, g, r outermost):
//    output bit-identical to previous rounds.

#define CR_HW 262144
#define PPT 4

#define F2FMA(d, a, b, c) \
    asm("fma.rn.f32x2 %0, %1, %2, %3;" : "=l"(d) : "l"(a), "l"(b), "l"(c))
#define F2PACK(d, lo, hi) \
    asm("mov.b64 %0, {%1, %2};" : "=l"(d) : "f"(lo), "f"(hi))
#define F2UNPACK(lo, hi, v) \
    asm("mov.b64 {%0, %1}, %2;" : "=f"(lo), "=f"(hi) : "l"(v))

typedef unsigned long long ull;

struct PalConst {
    // pair j covers colors (2j, 2j+1):
    //   pair2[j][0] = { {cx_2j, cx_2j+1}, {cy_2j, cy_2j+1} }
    //   pair2[j][1] = { {cz_2j, cz_2j+1}, {h_2j,  h_2j+1 } }
    ulonglong2 pair2[32][2];
    float4     palc[64];
};

__constant__ __align__(16) PalConst c_pal;
__device__  __align__(16) PalConst g_stage;

__global__ void prep_kernel(const float* __restrict__ pal)
{
    int t = threadIdx.x;
    if (t < 64) {
        float cx = pal[t * 3 + 0];
        float cy = pal[t * 3 + 1];
        float cz = pal[t * 3 + 2];
        float h  = -0.5f * (cx * cx + cy * cy + cz * cz);
        g_stage.palc[t] = make_float4(cx, cy, cz, h);
    }
    __syncthreads();
    if (t < 32) {
        float4 a = g_stage.palc[2 * t];
        float4 b = g_stage.palc[2 * t + 1];
        ull ux, uy, uz, uh;
        F2PACK(ux, a.x, b.x);
        F2PACK(uy, a.y, b.y);
        F2PACK(uz, a.z, b.z);
        F2PACK(uh, a.w, b.w);
        g_stage.pair2[t][0] = make_ulonglong2(ux, uy);
        g_stage.pair2[t][1] = make_ulonglong2(uz, uh);
    }
}

__global__ void __launch_bounds__(256, 5)
color_reduce_c_kernel(const float* __restrict__ x,
                      float* __restrict__ out,
                      int npix)
{
    // smem copy of compact palette (same bits as constants) for the
    // divergent-index finale + gather only.
    __shared__ float4 spalc[64];
    int t = threadIdx.x;
    if (t < 64) spalc[t] = c_pal.palc[t];
    __syncthreads();

    int gid = blockIdx.x * blockDim.x + t;
    int i0  = gid * PPT;
    if (i0 >= npix) return;

    int b = i0 >> 18;             // / CR_HW
    int q = i0 & (CR_HW - 1);

    const float* base  = x   + (size_t)b * 3 * CR_HW + q;
    float*       obase = out + (size_t)b * 3 * CR_HW + q;

    if (i0 + PPT - 1 < npix) {
        float4 pr = *reinterpret_cast<const float4*>(base);
        float4 pg = *reinterpret_cast<const float4*>(base + CR_HW);
        float4 pb = *reinterpret_cast<const float4*>(base + 2 * CR_HW);

        // per-pixel duplicated operands {v,v}; halves alias the scalars.
        ull rd[4], gd[4], bd[4];
        F2PACK(rd[0], pr.x, pr.x); F2PACK(rd[1], pr.y, pr.y);
        F2PACK(rd[2], pr.z, pr.z); F2PACK(rd[3], pr.w, pr.w);
        F2PACK(gd[0], pg.x, pg.x); F2PACK(gd[1], pg.y, pg.y);
        F2PACK(gd[2], pg.z, pg.z); F2PACK(gd[3], pg.w, pg.w);
        F2PACK(bd[0], pb.x, pb.x); F2PACK(bd[1], pb.y, pb.y);
        F2PACK(bd[2], pb.z, pb.z); F2PACK(bd[3], pb.w, pb.w);

        float best[4];
        int   bgrp[4];
#pragma unroll
        for (int p = 0; p < 4; p++) { best[p] = -FLT_MAX; bgrp[p] = 0; }

#pragma unroll
        for (int g = 0; g < 16; g++) {
            // group g = colors 4g..4g+3 = pairs 2g, 2g+1: 4x LDC.128 total
            ulonglong2 a0 = c_pal.pair2[2 * g + 0][0];   // {x01},{y01}
            ulonglong2 a1 = c_pal.pair2[2 * g + 0][1];   // {z01},{h01}
            ulonglong2 e0 = c_pal.pair2[2 * g + 1][0];   // {x23},{y23}
            ulonglong2 e1 = c_pal.pair2[2 * g + 1][1];   // {z23},{h23}

#pragma unroll
            for (int p = 0; p < 4; p++) {
                ull sA, sB;
                // sA halves = scores of colors 4g, 4g+1 for pixel p
                F2FMA(sA, bd[p], a1.x, a1.y);
                F2FMA(sA, gd[p], a0.y, sA);
                F2FMA(sA, rd[p], a0.x, sA);
                // sB halves = scores of colors 4g+2, 4g+3
                F2FMA(sB, bd[p], e1.x, e1.y);
                F2FMA(sB, gd[p], e0.y, sB);
                F2FMA(sB, rd[p], e0.x, sB);

                float s0, s1, s2, s3;
                F2UNPACK(s0, s1, sA);
                F2UNPACK(s2, s3, sB);

                float m = fmaxf(fmaxf(s0, s1), fmaxf(s2, s3));
                if (m > best[p]) { best[p] = m; bgrp[p] = g; }
            }
        }

        // finale: recompute winning group's 4 scores with identical FMA
        // nesting (b innermost) -> exact equality, first index wins.
        float4 cc[4];
#pragma unroll
        for (int p = 0; p < 4; p++) {
            float px, py, pz, dummy;
            F2UNPACK(px, dummy, rd[p]);
            F2UNPACK(py, dummy, gd[p]);
            F2UNPACK(pz, dummy, bd[p]);

            int k0 = bgrp[p] * 4;
            float4 c0 = spalc[k0 + 0];
            float4 c1 = spalc[k0 + 1];
            float4 c2 = spalc[k0 + 2];
            float4 c3 = spalc[k0 + 3];
            float s0 = fmaf(px, c0.x, fmaf(py, c0.y, fmaf(pz, c0.z, c0.w)));
            float s1 = fmaf(px, c1.x, fmaf(py, c1.y, fmaf(pz, c1.z, c1.w)));
            float s2 = fmaf(px, c2.x, fmaf(py, c2.y, fmaf(pz, c2.z, c2.w)));
            float s3 = fmaf(px, c3.x, fmaf(py, c3.y, fmaf(pz, c3.z, c3.w)));
            int j = 3;
            if (s2 == best[p]) j = 2;
            if (s1 == best[p]) j = 1;
            if (s0 == best[p]) j = 0;
            cc[p] = spalc[k0 + j];
        }

        *reinterpret_cast<float4*>(obase) =
            make_float4(cc[0].x, cc[1].x, cc[2].x, cc[3].x);
        *reinterpret_cast<float4*>(obase + CR_HW) =
            make_float4(cc[0].y, cc[1].y, cc[2].y, cc[3].y);
        *reinterpret_cast<float4*>(obase + 2 * CR_HW) =
            make_float4(cc[0].z, cc[1].z, cc[2].z, cc[3].z);
    } else {
        for (int i = i0; i < npix; i++) {
            int b2 = i >> 18;
            int q2 = i & (CR_HW - 1);
            const float* pb2 = x + (size_t)b2 * 3 * CR_HW + q2;
            float px = pb2[0], py = pb2[CR_HW], pz = pb2[2 * CR_HW];
            float bestv = -FLT_MAX; int bk = 0;
            for (int k = 0; k < 64; k++) {
                float4 c = spalc[k];
                float s = fmaf(px, c.x, fmaf(py, c.y, fmaf(pz, c.z, c.w)));
                if (s > bestv) { bestv = s; bk = k; }
            }
            float4 c = spalc[bk];
            float* ob = out + (size_t)b2 * 3 * CR_HW + q2;
            ob[0] = c.x; ob[CR_HW] = c.y; ob[2 * CR_HW] = c.z;
        }
    }
}

// generic fallback (any shape / ncol)
__global__ void color_reduce_generic_kernel(const float* __restrict__ x,
                                            const float* __restrict__ pal,
                                            float* __restrict__ out,
                                            int npix, int hw, int ncol)
{
    extern __shared__ float4 gpal[];
    int t = threadIdx.x;
    for (int k = t; k < ncol; k += blockDim.x) {
        float cx = pal[k * 3 + 0], cy = pal[k * 3 + 1], cz = pal[k * 3 + 2];
        gpal[k] = make_float4(cx, cy, cz, -0.5f * (cx * cx + cy * cy + cz * cz));
    }
    __syncthreads();
    int i = blockIdx.x * blockDim.x + t;
    if (i >= npix) return;
    int b = i / hw, q = i - b * hw;
    const float* pb = x + (size_t)b * 3 * (size_t)hw + q;
    float px = pb[0], py = pb[hw], pz = pb[2 * hw];
    float bestv = -FLT_MAX; int bk = 0;
    for (int k = 0; k < ncol; k++) {
        float4 c = gpal[k];
        float s = fmaf(px, c.x, fmaf(py, c.y, fmaf(pz, c.z, c.w)));
        if (s > bestv) { bestv = s; bk = k; }
    }
    float4 c = gpal[bk];
    float* ob = out + (size_t)b * 3 * (size_t)hw + q;
    ob[0] = c.x; ob[hw] = c.y; ob[2 * hw] = c.z;
}

extern "C" void kernel_launch(void* const* d_in, const int* in_sizes, int n_in,
                              void* d_out, int out_size)
{
    const float* x   = (const float*)d_in[0];
    const float* pal = (const float*)d_in[1];
    float*       out = (float*)d_out;

    int nelem = in_sizes[0];
    int ncol  = in_sizes[1] / 3;
    int npix  = nelem / 3;

    if (ncol == 64 && nelem % (3 * CR_HW) == 0) {
        prep_kernel<<<1, 64>>>(pal);

        void* ps = nullptr;
        cudaGetSymbolAddress(&ps, g_stage);
        cudaMemcpyToSymbolAsync(c_pal, ps, sizeof(PalConst), 0,
                                cudaMemcpyDeviceToDevice, 0);

        int threads = 256;
        int groups  = (npix + PPT - 1) / PPT;
        int blocks  = (groups + threads - 1) / threads;
        color_reduce_c_kernel<<<blocks, threads>>>(x, out, npix);
    } else {
        int hw = npix;
        if (nelem % (3 * CR_HW) == 0) hw = CR_HW;
        int threads = 256;
        int blocks  = (npix + threads - 1) / threads;
        color_reduce_generic_kernel<<<blocks, threads, ncol * sizeof(float4)>>>(
            x, pal, out, npix, hw, ncol);
    }
}